// round 4
// baseline (speedup 1.0000x reference)
#include <cuda_runtime.h>
#include <cuda_fp16.h>
#include <cstdint>

// Problem constants
#define BB 4
#define SS 2048
#define EE 1024
#define HH 16
#define DD 64
#define MM (BB*SS)   // 8192 rows

// ---------------------------------------------------------------------------
// Scratch (device globals)
// ---------------------------------------------------------------------------
__device__ __half g_Q[MM * EE];
__device__ __half g_K[MM * EE];
__device__ __half g_V[MM * EE];
__device__ __half g_A[MM * EE];
__device__ __half g_X[3][MM * EE];   // fp16-converted inputs q,k,v
__device__ __half g_W[4][EE * EE];   // fp16-converted weights Wq,Wk,Wv,Wo

// ---------------------------------------------------------------------------
// PTX helpers (legacy mma.sync path only — harness compiles for sm_100, no 'a')
// ---------------------------------------------------------------------------
__device__ __forceinline__ uint32_t smem_u32(const void* p) {
    return (uint32_t)__cvta_generic_to_shared(p);
}
__device__ __forceinline__ void ldmx4(uint32_t& r0, uint32_t& r1, uint32_t& r2,
                                      uint32_t& r3, uint32_t a) {
    asm volatile("ldmatrix.sync.aligned.m8n8.x4.shared.b16 {%0,%1,%2,%3}, [%4];\n"
                 : "=r"(r0), "=r"(r1), "=r"(r2), "=r"(r3) : "r"(a));
}
__device__ __forceinline__ void ldmx4t(uint32_t& r0, uint32_t& r1, uint32_t& r2,
                                       uint32_t& r3, uint32_t a) {
    asm volatile("ldmatrix.sync.aligned.m8n8.x4.trans.shared.b16 {%0,%1,%2,%3}, [%4];\n"
                 : "=r"(r0), "=r"(r1), "=r"(r2), "=r"(r3) : "r"(a));
}
__device__ __forceinline__ void mma16816(float* c, const uint32_t* a, const uint32_t* b) {
    asm volatile(
        "mma.sync.aligned.m16n8k16.row.col.f32.f16.f16.f32 "
        "{%0,%1,%2,%3}, {%4,%5,%6,%7}, {%8,%9}, {%0,%1,%2,%3};\n"
        : "+f"(c[0]), "+f"(c[1]), "+f"(c[2]), "+f"(c[3])
        : "r"(a[0]), "r"(a[1]), "r"(a[2]), "r"(a[3]), "r"(b[0]), "r"(b[1]));
}
__device__ __forceinline__ void cpa16(uint32_t dst, const void* src) {
    asm volatile("cp.async.cg.shared.global [%0], [%1], 16;\n" :: "r"(dst), "l"(src));
}
__device__ __forceinline__ void cpcommit() { asm volatile("cp.async.commit_group;\n"); }
template <int N>
__device__ __forceinline__ void cpwait() { asm volatile("cp.async.wait_group %0;\n" :: "n"(N)); }

// ---------------------------------------------------------------------------
// fp32 -> fp16 conversion of all inputs/weights in one pass
// ---------------------------------------------------------------------------
__global__ void cvt_kernel(const float* q, const float* k, const float* v,
                           const float* Wq, const float* Wk, const float* Wv,
                           const float* Wo) {
    const long X4 = (long)MM * EE / 4;
    const long W4 = (long)EE * EE / 4;
    const long total = 3 * X4 + 4 * W4;
    for (long i = (long)blockIdx.x * blockDim.x + threadIdx.x; i < total;
         i += (long)gridDim.x * blockDim.x) {
        const float* src; __half* dst; long off;
        if (i < X4)          { src = q; dst = g_X[0]; off = i; }
        else if (i < 2 * X4) { src = k; dst = g_X[1]; off = i - X4; }
        else if (i < 3 * X4) { src = v; dst = g_X[2]; off = i - 2 * X4; }
        else {
            long j = i - 3 * X4;
            int w = (int)(j >> 18);
            off = j & (W4 - 1);
            src = (w == 0) ? Wq : (w == 1) ? Wk : (w == 2) ? Wv : Wo;
            dst = g_W[w];
        }
        const float4 f = *(const float4*)(src + off * 4);
        const __half2 h0 = __floats2half2_rn(f.x, f.y);
        const __half2 h1 = __floats2half2_rn(f.z, f.w);
        uint2 h;
        h.x = *(const uint32_t*)&h0;
        h.y = *(const uint32_t*)&h1;
        *(uint2*)(dst + off * 4) = h;
    }
}

// ---------------------------------------------------------------------------
// GEMM: C[M,N] = A[M,K]*W[N,K]^T + bias, fp16 in / fp32 accum
// BM=BN=128, BK=64, 3-stage cp.async pipeline, 256 thr (4x2 warps, 32x64
// warp tile). Stride 72 halves = 144B: 16B-aligned for cp.async AND
// conflict-free for 8-row ldmatrix groups. 2 CTAs/SM.
// ---------------------------------------------------------------------------
#define BKg 64
#define KSTg 72
#define STGg 3
#define STAGE_Hg (128 * KSTg)       // halves per operand per stage (9216)
#define GEMM_SMEM (2 * STGg * STAGE_Hg * 2)   // 110592 B

template <bool O16>
__device__ __forceinline__ void gemm_body(const __half* Ag, const __half* Wg,
                                          const float* biasg, void* Cg_,
                                          __half* sA, __half* sB) {
    const int tid = threadIdx.x;
    const int bm = blockIdx.x, bn = blockIdx.y;
    const int warp = tid >> 5, lane = tid & 31;
    const int wm = warp & 3, wn = warp >> 2;

    // loader mapping: row = tid/2 (0..127), half the row (32 halves) per thread
    const int lrow = tid >> 1;
    const int lcb  = (tid & 1) * 32;            // halves
    const __half* gA = Ag + (long)(bm * 128) * EE;
    const __half* gB = Wg + (long)(bn * 128) * EE;
    const uint32_t sAb = smem_u32(sA);
    const uint32_t sBb = smem_u32(sB);

    const int NK = EE / BKg;                    // 16

    auto issue = [&](int kt, int buf) {
        const uint32_t dA = sAb + (buf * STAGE_Hg + lrow * KSTg + lcb) * 2;
        const uint32_t dB = sBb + (buf * STAGE_Hg + lrow * KSTg + lcb) * 2;
        const __half* srcA = gA + (long)lrow * EE + kt * BKg + lcb;
        const __half* srcB = gB + (long)lrow * EE + kt * BKg + lcb;
#pragma unroll
        for (int i = 0; i < 4; i++) {
            cpa16(dA + i * 16, srcA + i * 8);
            cpa16(dB + i * 16, srcB + i * 8);
        }
    };

    issue(0, 0); cpcommit();
    issue(1, 1); cpcommit();

    float acc[2][8][4];
#pragma unroll
    for (int j = 0; j < 2; j++)
#pragma unroll
        for (int n = 0; n < 8; n++)
#pragma unroll
            for (int v = 0; v < 4; v++) acc[j][n][v] = 0.f;

    for (int kt = 0; kt < NK; kt++) {
        cpwait<1>();
        __syncthreads();
        {
            const int nk = (kt + 2 < NK) ? kt + 2 : NK - 1;
            issue(nk, (kt + 2) % STGg);
            cpcommit();
        }
        const __half* cA = sA + (kt % STGg) * STAGE_Hg;
        const __half* cB = sB + (kt % STGg) * STAGE_Hg;
#pragma unroll
        for (int ks = 0; ks < 4; ks++) {
            const int kb = ks * 16;
            uint32_t af[2][4];
#pragma unroll
            for (int j = 0; j < 2; j++) {
                const uint32_t ad = smem_u32(
                    cA + (wm * 32 + j * 16 + (lane & 15)) * KSTg + kb + (lane >> 4) * 8);
                ldmx4(af[j][0], af[j][1], af[j][2], af[j][3], ad);
            }
            uint32_t bf[8][2];
#pragma unroll
            for (int q = 0; q < 4; q++) {
                const int nrow = wn * 64 + q * 16 + (lane & 7) + ((lane >> 4) << 3);
                const int koff = ((lane >> 3) & 1) * 8;
                const uint32_t ad = smem_u32(cB + nrow * KSTg + kb + koff);
                ldmx4(bf[2 * q][0], bf[2 * q][1], bf[2 * q + 1][0], bf[2 * q + 1][1], ad);
            }
#pragma unroll
            for (int j = 0; j < 2; j++)
#pragma unroll
                for (int n = 0; n < 8; n++) mma16816(acc[j][n], af[j], bf[n]);
        }
        __syncthreads();
    }

    // Epilogue: + bias, store
#pragma unroll
    for (int j = 0; j < 2; j++) {
#pragma unroll
        for (int n = 0; n < 8; n++) {
            const int row = bm * 128 + wm * 32 + j * 16 + (lane >> 2);
            const int col = bn * 128 + wn * 64 + n * 8 + (lane & 3) * 2;
            const float b0 = biasg[col], b1 = biasg[col + 1];
            const float c0 = acc[j][n][0] + b0, c1 = acc[j][n][1] + b1;
            const float c2 = acc[j][n][2] + b0, c3 = acc[j][n][3] + b1;
            if (O16) {
                __half* C = (__half*)Cg_;
                *(__half2*)(C + (long)row * EE + col)       = __floats2half2_rn(c0, c1);
                *(__half2*)(C + (long)(row + 8) * EE + col) = __floats2half2_rn(c2, c3);
            } else {
                float* C = (float*)Cg_;
                *(float2*)(C + (long)row * EE + col)       = make_float2(c0, c1);
                *(float2*)(C + (long)(row + 8) * EE + col) = make_float2(c2, c3);
            }
        }
    }
}

__global__ __launch_bounds__(256, 2) void qkv_kernel(const float* bq, const float* bk,
                                                     const float* bv) {
    extern __shared__ __half sm_g[];
    const int z = blockIdx.z;
    const float* bias = (z == 0) ? bq : (z == 1) ? bk : bv;
    __half* O = (z == 0) ? g_Q : (z == 1) ? g_K : g_V;
    gemm_body<true>(g_X[z], g_W[z], bias, O, sm_g, sm_g + STGg * STAGE_Hg);
}

__global__ __launch_bounds__(256, 2) void oproj_kernel(const float* bo, float* out) {
    extern __shared__ __half sm_g[];
    gemm_body<false>(g_A, g_W[3], bo, out, sm_g, sm_g + STGg * STAGE_Hg);
}

// ---------------------------------------------------------------------------
// Flash attention: CTA = (b, h, 128 queries), 8 warps x 16 q-rows.
// KV tiles of 64 rows, 3-stage cp.async. Q fragments pre-scaled by
// scale*log2(e); softmax exp via ex2.approx.f16x2 (h2exp2) -> packed fp16 P
// directly; row sums kept in fp32.
// ---------------------------------------------------------------------------
#define QT 128
#define KT 64
#define AST 72
#define KVSTG_H (KT * AST)

__global__ __launch_bounds__(256, 1) void attn_kernel() {
    extern __shared__ __half sm_a[];
    __half* sQ = sm_a;
    __half* sK = sQ + QT * AST;
    __half* sV = sK + 3 * KVSTG_H;

    const int tid  = threadIdx.x;
    const int warp = tid >> 5, lane = tid & 31;
    const int qbase = blockIdx.x * QT;
    const int h     = blockIdx.y;
    const int b     = blockIdx.z;
    const long rowbase = (long)b * SS;
    const int colbase  = h * DD;

    const uint32_t sKb = smem_u32(sK);
    const uint32_t sVb = smem_u32(sV);

    const int krow = tid >> 3;
    const int kch  = (tid & 7) * 8;
    const int NT = SS / KT;

    auto issueKV = [&](int t, int buf) {
        const long gb = (rowbase + t * KT) * EE + colbase + kch;
        const uint32_t dK = sKb + buf * KVSTG_H * 2 + (krow * AST + kch) * 2;
        const uint32_t dV = sVb + buf * KVSTG_H * 2 + (krow * AST + kch) * 2;
        cpa16(dK,                g_K + gb + (long)krow * EE);
        cpa16(dK + 32 * AST * 2, g_K + gb + (long)(krow + 32) * EE);
        cpa16(dV,                g_V + gb + (long)krow * EE);
        cpa16(dV + 32 * AST * 2, g_V + gb + (long)(krow + 32) * EE);
    };

    issueKV(0, 0); cpcommit();
    issueKV(1, 1); cpcommit();

    {
        const int lr = tid >> 3;
        const int lc = (tid & 7) * 8;
#pragma unroll
        for (int i = 0; i < 4; i++) {
            const int row = lr + i * 32;
            const uint4 v = *(const uint4*)(g_Q + (rowbase + qbase + row) * EE + colbase + lc);
            *(uint4*)(sQ + row * AST + lc) = v;
        }
    }
    __syncthreads();

    // Persistent Q fragments, pre-scaled by scale*log2(e)
    const float SC = 0.125f * 1.4426950408889634f;
    uint32_t qa[4][4];
    {
        const int wq = warp * 16;
        const __half2 sc2 = __floats2half2_rn(SC, SC);
#pragma unroll
        for (int kk = 0; kk < 4; kk++) {
            const uint32_t ad =
                smem_u32(sQ + (wq + (lane & 15)) * AST + kk * 16 + (lane >> 4) * 8);
            ldmx4(qa[kk][0], qa[kk][1], qa[kk][2], qa[kk][3], ad);
#pragma unroll
            for (int r = 0; r < 4; r++) {
                __half2 q2 = *(const __half2*)&qa[kk][r];
                q2 = __hmul2(q2, sc2);
                qa[kk][r] = *(const uint32_t*)&q2;
            }
        }
    }

    float oacc[8][4];
#pragma unroll
    for (int n = 0; n < 8; n++)
#pragma unroll
        for (int v = 0; v < 4; v++) oacc[n][v] = 0.f;
    float m0 = -1e30f, m1 = -1e30f, l0 = 0.f, l1 = 0.f;

    for (int t = 0; t < NT; t++) {
        cpwait<1>();
        __syncthreads();
        {
            const int nt = (t + 2 < NT) ? t + 2 : NT - 1;
            issueKV(nt, (t + 2) % 3);
            cpcommit();
        }
        const __half* cK = sK + (t % 3) * KVSTG_H;
        const __half* cV = sV + (t % 3) * KVSTG_H;

        // S = Q K^T (already in log2 units: Q pre-scaled)
        float sacc[8][4];
#pragma unroll
        for (int n = 0; n < 8; n++)
#pragma unroll
            for (int v = 0; v < 4; v++) sacc[n][v] = 0.f;
#pragma unroll
        for (int kk = 0; kk < 4; kk++) {
            uint32_t kb[8][2];
#pragma unroll
            for (int q = 0; q < 4; q++) {
                const int nrow = q * 16 + (lane & 7) + ((lane >> 4) << 3);
                const int koff = ((lane >> 3) & 1) * 8;
                const uint32_t ad = smem_u32(cK + nrow * AST + kk * 16 + koff);
                ldmx4(kb[2 * q][0], kb[2 * q][1], kb[2 * q + 1][0], kb[2 * q + 1][1], ad);
            }
#pragma unroll
            for (int n = 0; n < 8; n++) mma16816(sacc[n], qa[kk], kb[n]);
        }

        // Online softmax in base-2 units
        float mx0 = -1e30f, mx1 = -1e30f;
#pragma unroll
        for (int n = 0; n < 8; n++) {
            mx0 = fmaxf(mx0, fmaxf(sacc[n][0], sacc[n][1]));
            mx1 = fmaxf(mx1, fmaxf(sacc[n][2], sacc[n][3]));
        }
        mx0 = fmaxf(mx0, __shfl_xor_sync(0xffffffffu, mx0, 1));
        mx0 = fmaxf(mx0, __shfl_xor_sync(0xffffffffu, mx0, 2));
        mx1 = fmaxf(mx1, __shfl_xor_sync(0xffffffffu, mx1, 1));
        mx1 = fmaxf(mx1, __shfl_xor_sync(0xffffffffu, mx1, 2));
        const float nm0 = fmaxf(m0, mx0);
        const float nm1 = fmaxf(m1, mx1);
        const float cr0 = exp2f(m0 - nm0);
        const float cr1 = exp2f(m1 - nm1);
        m0 = nm0; m1 = nm1;
        l0 *= cr0; l1 *= cr1;
#pragma unroll
        for (int n = 0; n < 8; n++) {
            oacc[n][0] *= cr0; oacc[n][1] *= cr0;
            oacc[n][2] *= cr1; oacc[n][3] *= cr1;
        }
        // exp via f16x2 MUFU -> packed P fragments; row sums in fp32
        float rs0 = 0.f, rs1 = 0.f;
        uint32_t pa[8], pb[8];
#pragma unroll
        for (int n = 0; n < 8; n++) {
            const __half2 e01 =
                h2exp2(__floats2half2_rn(sacc[n][0] - m0, sacc[n][1] - m0));
            const __half2 e23 =
                h2exp2(__floats2half2_rn(sacc[n][2] - m1, sacc[n][3] - m1));
            pa[n] = *(const uint32_t*)&e01;
            pb[n] = *(const uint32_t*)&e23;
            const float2 f01 = __half22float2(e01);
            const float2 f23 = __half22float2(e23);
            rs0 += f01.x + f01.y;
            rs1 += f23.x + f23.y;
        }
        rs0 += __shfl_xor_sync(0xffffffffu, rs0, 1);
        rs0 += __shfl_xor_sync(0xffffffffu, rs0, 2);
        rs1 += __shfl_xor_sync(0xffffffffu, rs1, 1);
        rs1 += __shfl_xor_sync(0xffffffffu, rs1, 2);
        l0 += rs0; l1 += rs1;

        // O += P V (P already in A-fragment layout)
#pragma unroll
        for (int kk = 0; kk < 4; kk++) {
            const uint32_t af[4] = {pa[2 * kk], pb[2 * kk], pa[2 * kk + 1], pb[2 * kk + 1]};
            uint32_t vb[8][2];
#pragma unroll
            for (int pr = 0; pr < 4; pr++) {
                const int kvrow = kk * 16 + (((lane >> 3) & 1) << 3) + (lane & 7);
                const int dcol  = pr * 16 + ((lane >> 4) << 3);
                const uint32_t ad = smem_u32(cV + kvrow * AST + dcol);
                ldmx4t(vb[2 * pr][0], vb[2 * pr][1], vb[2 * pr + 1][0], vb[2 * pr + 1][1], ad);
            }
#pragma unroll
            for (int n = 0; n < 8; n++) mma16816(oacc[n], af, vb[n]);
        }
    }

    // Epilogue
    const float il0 = 1.f / l0, il1 = 1.f / l1;
    const int row = qbase + warp * 16 + (lane >> 2);
#pragma unroll
    for (int n = 0; n < 8; n++) {
        const int col = colbase + n * 8 + (lane & 3) * 2;
        *(__half2*)(g_A + (rowbase + row) * EE + col) =
            __floats2half2_rn(oacc[n][0] * il0, oacc[n][1] * il0);
        *(__half2*)(g_A + (rowbase + row + 8) * EE + col) =
            __floats2half2_rn(oacc[n][2] * il1, oacc[n][3] * il1);
    }
}

// ---------------------------------------------------------------------------
// Launch
// ---------------------------------------------------------------------------
extern "C" void kernel_launch(void* const* d_in, const int* in_sizes, int n_in,
                              void* d_out, int out_size) {
    (void)in_sizes; (void)n_in; (void)out_size;
    const float* q  = (const float*)d_in[0];
    const float* k  = (const float*)d_in[1];
    const float* v  = (const float*)d_in[2];
    const float* Wq = (const float*)d_in[3];
    const float* bq = (const float*)d_in[4];
    const float* Wk = (const float*)d_in[5];
    const float* bk = (const float*)d_in[6];
    const float* Wv = (const float*)d_in[7];
    const float* bv = (const float*)d_in[8];
    const float* Wo = (const float*)d_in[9];
    const float* bo = (const float*)d_in[10];

    const int attn_smem = (QT * AST + 6 * KVSTG_H) * 2;           // 73728 B
    cudaFuncSetAttribute(qkv_kernel,   cudaFuncAttributeMaxDynamicSharedMemorySize, GEMM_SMEM);
    cudaFuncSetAttribute(oproj_kernel, cudaFuncAttributeMaxDynamicSharedMemorySize, GEMM_SMEM);
    cudaFuncSetAttribute(attn_kernel,  cudaFuncAttributeMaxDynamicSharedMemorySize, attn_smem);

    cvt_kernel<<<4096, 256>>>(q, k, v, Wq, Wk, Wv, Wo);

    dim3 g1(MM / 128, EE / 128, 3);
    qkv_kernel<<<g1, 256, GEMM_SMEM>>>(bq, bk, bv);

    dim3 g2(SS / QT, HH, BB);
    attn_kernel<<<g2, 256, attn_smem>>>();

    dim3 g3(MM / 128, EE / 128, 1);
    oproj_kernel<<<g3, 256, GEMM_SMEM>>>(bo, (float*)d_out);
}

// round 7
// speedup vs baseline: 1.2664x; 1.2664x over previous
#include <cuda_runtime.h>
#include <cuda_fp16.h>
#include <cstdint>

// Problem constants
#define BB 4
#define SS 2048
#define EE 1024
#define HH 16
#define DD 64
#define MM (BB*SS)   // 8192 rows

// ---------------------------------------------------------------------------
// Scratch (device globals)
// ---------------------------------------------------------------------------
__device__ __half g_Q[MM * EE];
__device__ __half g_K[MM * EE];
__device__ __half g_V[MM * EE];
__device__ __half g_A[MM * EE];
__device__ __half g_X[3][MM * EE];   // fp16-converted inputs q,k,v
__device__ __half g_W[4][EE * EE];   // fp16-converted weights Wq,Wk,Wv,Wo

// ---------------------------------------------------------------------------
// PTX helpers (legacy mma.sync path — harness targets sm_100, no tcgen05)
// ---------------------------------------------------------------------------
__device__ __forceinline__ uint32_t smem_u32(const void* p) {
    return (uint32_t)__cvta_generic_to_shared(p);
}
__device__ __forceinline__ void ldmx4(uint32_t& r0, uint32_t& r1, uint32_t& r2,
                                      uint32_t& r3, uint32_t a) {
    asm volatile("ldmatrix.sync.aligned.m8n8.x4.shared.b16 {%0,%1,%2,%3}, [%4];\n"
                 : "=r"(r0), "=r"(r1), "=r"(r2), "=r"(r3) : "r"(a));
}
__device__ __forceinline__ void ldmx4t(uint32_t& r0, uint32_t& r1, uint32_t& r2,
                                       uint32_t& r3, uint32_t a) {
    asm volatile("ldmatrix.sync.aligned.m8n8.x4.trans.shared.b16 {%0,%1,%2,%3}, [%4];\n"
                 : "=r"(r0), "=r"(r1), "=r"(r2), "=r"(r3) : "r"(a));
}
__device__ __forceinline__ void mma16816(float* c, const uint32_t* a, const uint32_t* b) {
    asm volatile(
        "mma.sync.aligned.m16n8k16.row.col.f32.f16.f16.f32 "
        "{%0,%1,%2,%3}, {%4,%5,%6,%7}, {%8,%9}, {%0,%1,%2,%3};\n"
        : "+f"(c[0]), "+f"(c[1]), "+f"(c[2]), "+f"(c[3])
        : "r"(a[0]), "r"(a[1]), "r"(a[2]), "r"(a[3]), "r"(b[0]), "r"(b[1]));
}
__device__ __forceinline__ void cpa16(uint32_t dst, const void* src) {
    asm volatile("cp.async.cg.shared.global [%0], [%1], 16;\n" :: "r"(dst), "l"(src));
}
__device__ __forceinline__ void cpcommit() { asm volatile("cp.async.commit_group;\n"); }
template <int N>
__device__ __forceinline__ void cpwait() { asm volatile("cp.async.wait_group %0;\n" :: "n"(N)); }

// ---------------------------------------------------------------------------
// fp32 -> fp16 conversion of all inputs/weights in one pass
// ---------------------------------------------------------------------------
__global__ void cvt_kernel(const float* q, const float* k, const float* v,
                           const float* Wq, const float* Wk, const float* Wv,
                           const float* Wo) {
    const long X4 = (long)MM * EE / 4;
    const long W4 = (long)EE * EE / 4;
    const long total = 3 * X4 + 4 * W4;
    for (long i = (long)blockIdx.x * blockDim.x + threadIdx.x; i < total;
         i += (long)gridDim.x * blockDim.x) {
        const float* src; __half* dst; long off;
        if (i < X4)          { src = q; dst = g_X[0]; off = i; }
        else if (i < 2 * X4) { src = k; dst = g_X[1]; off = i - X4; }
        else if (i < 3 * X4) { src = v; dst = g_X[2]; off = i - 2 * X4; }
        else {
            long j = i - 3 * X4;
            int w = (int)(j >> 18);
            off = j & (W4 - 1);
            src = (w == 0) ? Wq : (w == 1) ? Wk : (w == 2) ? Wv : Wo;
            dst = g_W[w];
        }
        const float4 f = *(const float4*)(src + off * 4);
        const __half2 h0 = __floats2half2_rn(f.x, f.y);
        const __half2 h1 = __floats2half2_rn(f.z, f.w);
        uint2 h;
        h.x = *(const uint32_t*)&h0;
        h.y = *(const uint32_t*)&h1;
        *(uint2*)(dst + off * 4) = h;
    }
}

// ---------------------------------------------------------------------------
// GEMM: C[M,N] = A[M,K]*W[N,K]^T + bias, fp16 in / fp32 accum
// Round-2 proven layout: BM=BN=128, BK=32, stride 40 halves (80B).
// 4-stage cp.async pipeline (prefetch depth 3), ONE barrier per k-tile.
// 256 thr (4x2 warps, 32x64 warp tile), 2 CTAs/SM.
// ---------------------------------------------------------------------------
#define BK 32
#define KST 40
#define STG 4
#define STAGE_H (128 * KST)                  // 5120 halves per operand/stage
#define GEMM_SMEM (2 * STG * STAGE_H * 2)    // 81920 B

template <bool O16>
__device__ __forceinline__ void gemm_body(const __half* Ag, const __half* Wg,
                                          const float* biasg, void* Cg_,
                                          __half* sA, __half* sB) {
    const int tid = threadIdx.x;
    const int bm = blockIdx.x, bn = blockIdx.y;
    const int warp = tid >> 5, lane = tid & 31;
    const int wm = warp & 3, wn = warp >> 2;

    // cp.async mapping: row = tid/4 (0..63, +64), 16B chunk = tid&3
    const int lrow = tid >> 2;
    const int lch  = (tid & 3) * 8;          // halves
    const __half* gA = Ag + (long)(bm * 128) * EE;
    const __half* gB = Wg + (long)(bn * 128) * EE;
    const uint32_t sAb = smem_u32(sA);
    const uint32_t sBb = smem_u32(sB);

    const int NK = EE / BK;                  // 32

    auto issue = [&](int kt, int buf) {
        const int kb = kt * BK + lch;
        const uint32_t dA = sAb + (buf * STAGE_H + lrow * KST + lch) * 2;
        const uint32_t dB = sBb + (buf * STAGE_H + lrow * KST + lch) * 2;
        cpa16(dA,               gA + (long)lrow * EE + kb);
        cpa16(dA + 64 * KST * 2, gA + (long)(lrow + 64) * EE + kb);
        cpa16(dB,               gB + (long)lrow * EE + kb);
        cpa16(dB + 64 * KST * 2, gB + (long)(lrow + 64) * EE + kb);
    };

    issue(0, 0); cpcommit();
    issue(1, 1); cpcommit();
    issue(2, 2); cpcommit();

    float acc[2][8][4];
#pragma unroll
    for (int j = 0; j < 2; j++)
#pragma unroll
        for (int n = 0; n < 8; n++)
#pragma unroll
            for (int v = 0; v < 4; v++) acc[j][n][v] = 0.f;

    for (int kt = 0; kt < NK; kt++) {
        cpwait<2>();            // stage kt landed (kt+1, kt+2 may be pending)
        __syncthreads();        // deposits visible + all warps done reading the
                                // stage about to be overwritten below
        {
            const int nk = (kt + 3 < NK) ? kt + 3 : NK - 1;
            issue(nk, (kt + 3) % STG);
            cpcommit();
        }
        const __half* cA = sA + (kt % STG) * STAGE_H;
        const __half* cB = sB + (kt % STG) * STAGE_H;
#pragma unroll
        for (int ks = 0; ks < 2; ks++) {
            const int kb = ks * 16;
            uint32_t af[2][4];
#pragma unroll
            for (int j = 0; j < 2; j++) {
                const uint32_t ad = smem_u32(
                    cA + (wm * 32 + j * 16 + (lane & 15)) * KST + kb + (lane >> 4) * 8);
                ldmx4(af[j][0], af[j][1], af[j][2], af[j][3], ad);
            }
            uint32_t bf[8][2];
#pragma unroll
            for (int q = 0; q < 4; q++) {
                const int nrow = wn * 64 + q * 16 + (lane & 7) + ((lane >> 4) << 3);
                const int koff = ((lane >> 3) & 1) * 8;
                const uint32_t ad = smem_u32(cB + nrow * KST + kb + koff);
                ldmx4(bf[2 * q][0], bf[2 * q][1], bf[2 * q + 1][0], bf[2 * q + 1][1], ad);
            }
#pragma unroll
            for (int j = 0; j < 2; j++)
#pragma unroll
                for (int n = 0; n < 8; n++) mma16816(acc[j][n], af[j], bf[n]);
        }
    }

    // Epilogue: + bias, store
#pragma unroll
    for (int j = 0; j < 2; j++) {
#pragma unroll
        for (int n = 0; n < 8; n++) {
            const int row = bm * 128 + wm * 32 + j * 16 + (lane >> 2);
            const int col = bn * 128 + wn * 64 + n * 8 + (lane & 3) * 2;
            const float b0 = biasg[col], b1 = biasg[col + 1];
            const float c0 = acc[j][n][0] + b0, c1 = acc[j][n][1] + b1;
            const float c2 = acc[j][n][2] + b0, c3 = acc[j][n][3] + b1;
            if (O16) {
                __half* C = (__half*)Cg_;
                *(__half2*)(C + (long)row * EE + col)       = __floats2half2_rn(c0, c1);
                *(__half2*)(C + (long)(row + 8) * EE + col) = __floats2half2_rn(c2, c3);
            } else {
                float* C = (float*)Cg_;
                *(float2*)(C + (long)row * EE + col)       = make_float2(c0, c1);
                *(float2*)(C + (long)(row + 8) * EE + col) = make_float2(c2, c3);
            }
        }
    }
}

__global__ __launch_bounds__(256, 2) void qkv_kernel(const float* bq, const float* bk,
                                                     const float* bv) {
    extern __shared__ __half sm_g[];
    const int z = blockIdx.z;
    const float* bias = (z == 0) ? bq : (z == 1) ? bk : bv;
    __half* O = (z == 0) ? g_Q : (z == 1) ? g_K : g_V;
    gemm_body<true>(g_X[z], g_W[z], bias, O, sm_g, sm_g + STG * STAGE_H);
}

__global__ __launch_bounds__(256, 2) void oproj_kernel(const float* bo, float* out) {
    extern __shared__ __half sm_g[];
    gemm_body<false>(g_A, g_W[3], bo, out, sm_g, sm_g + STG * STAGE_H);
}

// ---------------------------------------------------------------------------
// Flash attention: CTA = (b, h, 128 queries), 8 warps x 16 q-rows.
// KV tiles of 64 rows, 3-stage cp.async. Q pre-scaled by scale*log2(e);
// exp via ex2.approx.f16x2. 2 CTAs/SM (128-reg cap) to hide latency.
// ---------------------------------------------------------------------------
#define QT 128
#define KT 64
#define AST 72
#define KVSTG_H (KT * AST)

__global__ __launch_bounds__(256, 2) void attn_kernel() {
    extern __shared__ __half sm_a[];
    __half* sQ = sm_a;
    __half* sK = sQ + QT * AST;
    __half* sV = sK + 3 * KVSTG_H;

    const int tid  = threadIdx.x;
    const int warp = tid >> 5, lane = tid & 31;
    const int qbase = blockIdx.x * QT;
    const int h     = blockIdx.y;
    const int b     = blockIdx.z;
    const long rowbase = (long)b * SS;
    const int colbase  = h * DD;

    const uint32_t sKb = smem_u32(sK);
    const uint32_t sVb = smem_u32(sV);

    const int krow = tid >> 3;
    const int kch  = (tid & 7) * 8;
    const int NT = SS / KT;

    auto issueKV = [&](int t, int buf) {
        const long gb = (rowbase + t * KT) * EE + colbase + kch;
        const uint32_t dK = sKb + buf * KVSTG_H * 2 + (krow * AST + kch) * 2;
        const uint32_t dV = sVb + buf * KVSTG_H * 2 + (krow * AST + kch) * 2;
        cpa16(dK,                g_K + gb + (long)krow * EE);
        cpa16(dK + 32 * AST * 2, g_K + gb + (long)(krow + 32) * EE);
        cpa16(dV,                g_V + gb + (long)krow * EE);
        cpa16(dV + 32 * AST * 2, g_V + gb + (long)(krow + 32) * EE);
    };

    issueKV(0, 0); cpcommit();
    issueKV(1, 1); cpcommit();

    {
        const int lr = tid >> 3;
        const int lc = (tid & 7) * 8;
#pragma unroll
        for (int i = 0; i < 4; i++) {
            const int row = lr + i * 32;
            const uint4 v = *(const uint4*)(g_Q + (rowbase + qbase + row) * EE + colbase + lc);
            *(uint4*)(sQ + row * AST + lc) = v;
        }
    }
    __syncthreads();

    // Persistent Q fragments, pre-scaled by scale*log2(e)
    const float SC = 0.125f * 1.4426950408889634f;
    uint32_t qa[4][4];
    {
        const int wq = warp * 16;
        const __half2 sc2 = __floats2half2_rn(SC, SC);
#pragma unroll
        for (int kk = 0; kk < 4; kk++) {
            const uint32_t ad =
                smem_u32(sQ + (wq + (lane & 15)) * AST + kk * 16 + (lane >> 4) * 8);
            ldmx4(qa[kk][0], qa[kk][1], qa[kk][2], qa[kk][3], ad);
#pragma unroll
            for (int r = 0; r < 4; r++) {
                __half2 q2 = *(const __half2*)&qa[kk][r];
                q2 = __hmul2(q2, sc2);
                qa[kk][r] = *(const uint32_t*)&q2;
            }
        }
    }

    float oacc[8][4];
#pragma unroll
    for (int n = 0; n < 8; n++)
#pragma unroll
        for (int v = 0; v < 4; v++) oacc[n][v] = 0.f;
    float m0 = -1e30f, m1 = -1e30f, l0 = 0.f, l1 = 0.f;

    for (int t = 0; t < NT; t++) {
        cpwait<1>();
        __syncthreads();
        {
            const int nt = (t + 2 < NT) ? t + 2 : NT - 1;
            issueKV(nt, (t + 2) % 3);
            cpcommit();
        }
        const __half* cK = sK + (t % 3) * KVSTG_H;
        const __half* cV = sV + (t % 3) * KVSTG_H;

        // S = Q K^T (log2 units: Q pre-scaled)
        float sacc[8][4];
#pragma unroll
        for (int n = 0; n < 8; n++)
#pragma unroll
            for (int v = 0; v < 4; v++) sacc[n][v] = 0.f;
#pragma unroll
        for (int kk = 0; kk < 4; kk++) {
            uint32_t kb[8][2];
#pragma unroll
            for (int q = 0; q < 4; q++) {
                const int nrow = q * 16 + (lane & 7) + ((lane >> 4) << 3);
                const int koff = ((lane >> 3) & 1) * 8;
                const uint32_t ad = smem_u32(cK + nrow * AST + kk * 16 + koff);
                ldmx4(kb[2 * q][0], kb[2 * q][1], kb[2 * q + 1][0], kb[2 * q + 1][1], ad);
            }
#pragma unroll
            for (int n = 0; n < 8; n++) mma16816(sacc[n], qa[kk], kb[n]);
        }

        // Online softmax in base-2 units
        float mx0 = -1e30f, mx1 = -1e30f;
#pragma unroll
        for (int n = 0; n < 8; n++) {
            mx0 = fmaxf(mx0, fmaxf(sacc[n][0], sacc[n][1]));
            mx1 = fmaxf(mx1, fmaxf(sacc[n][2], sacc[n][3]));
        }
        mx0 = fmaxf(mx0, __shfl_xor_sync(0xffffffffu, mx0, 1));
        mx0 = fmaxf(mx0, __shfl_xor_sync(0xffffffffu, mx0, 2));
        mx1 = fmaxf(mx1, __shfl_xor_sync(0xffffffffu, mx1, 1));
        mx1 = fmaxf(mx1, __shfl_xor_sync(0xffffffffu, mx1, 2));
        const float nm0 = fmaxf(m0, mx0);
        const float nm1 = fmaxf(m1, mx1);
        const float cr0 = exp2f(m0 - nm0);
        const float cr1 = exp2f(m1 - nm1);
        m0 = nm0; m1 = nm1;
        l0 *= cr0; l1 *= cr1;
#pragma unroll
        for (int n = 0; n < 8; n++) {
            oacc[n][0] *= cr0; oacc[n][1] *= cr0;
            oacc[n][2] *= cr1; oacc[n][3] *= cr1;
        }
        float rs0 = 0.f, rs1 = 0.f;
        uint32_t pa[8], pb[8];
#pragma unroll
        for (int n = 0; n < 8; n++) {
            const __half2 e01 =
                h2exp2(__floats2half2_rn(sacc[n][0] - m0, sacc[n][1] - m0));
            const __half2 e23 =
                h2exp2(__floats2half2_rn(sacc[n][2] - m1, sacc[n][3] - m1));
            pa[n] = *(const uint32_t*)&e01;
            pb[n] = *(const uint32_t*)&e23;
            const float2 f01 = __half22float2(e01);
            const float2 f23 = __half22float2(e23);
            rs0 += f01.x + f01.y;
            rs1 += f23.x + f23.y;
        }
        rs0 += __shfl_xor_sync(0xffffffffu, rs0, 1);
        rs0 += __shfl_xor_sync(0xffffffffu, rs0, 2);
        rs1 += __shfl_xor_sync(0xffffffffu, rs1, 1);
        rs1 += __shfl_xor_sync(0xffffffffu, rs1, 2);
        l0 += rs0; l1 += rs1;

        // O += P V (P already in A-fragment layout)
#pragma unroll
        for (int kk = 0; kk < 4; kk++) {
            const uint32_t af[4] = {pa[2 * kk], pb[2 * kk], pa[2 * kk + 1], pb[2 * kk + 1]};
            uint32_t vb[8][2];
#pragma unroll
            for (int pr = 0; pr < 4; pr++) {
                const int kvrow = kk * 16 + (((lane >> 3) & 1) << 3) + (lane & 7);
                const int dcol  = pr * 16 + ((lane >> 4) << 3);
                const uint32_t ad = smem_u32(cV + kvrow * AST + dcol);
                ldmx4t(vb[2 * pr][0], vb[2 * pr][1], vb[2 * pr + 1][0], vb[2 * pr + 1][1], ad);
            }
#pragma unroll
            for (int n = 0; n < 8; n++) mma16816(oacc[n], af, vb[n]);
        }
    }

    // Epilogue
    const float il0 = 1.f / l0, il1 = 1.f / l1;
    const int row = qbase + warp * 16 + (lane >> 2);
#pragma unroll
    for (int n = 0; n < 8; n++) {
        const int col = colbase + n * 8 + (lane & 3) * 2;
        *(__half2*)(g_A + (rowbase + row) * EE + col) =
            __floats2half2_rn(oacc[n][0] * il0, oacc[n][1] * il0);
        *(__half2*)(g_A + (rowbase + row + 8) * EE + col) =
            __floats2half2_rn(oacc[n][2] * il1, oacc[n][3] * il1);
    }
}

// ---------------------------------------------------------------------------
// Launch
// ---------------------------------------------------------------------------
extern "C" void kernel_launch(void* const* d_in, const int* in_sizes, int n_in,
                              void* d_out, int out_size) {
    (void)in_sizes; (void)n_in; (void)out_size;
    const float* q  = (const float*)d_in[0];
    const float* k  = (const float*)d_in[1];
    const float* v  = (const float*)d_in[2];
    const float* Wq = (const float*)d_in[3];
    const float* bq = (const float*)d_in[4];
    const float* Wk = (const float*)d_in[5];
    const float* bk = (const float*)d_in[6];
    const float* Wv = (const float*)d_in[7];
    const float* bv = (const float*)d_in[8];
    const float* Wo = (const float*)d_in[9];
    const float* bo = (const float*)d_in[10];

    const int attn_smem = (QT * AST + 6 * KVSTG_H) * 2;           // 73728 B
    cudaFuncSetAttribute(qkv_kernel,   cudaFuncAttributeMaxDynamicSharedMemorySize, GEMM_SMEM);
    cudaFuncSetAttribute(oproj_kernel, cudaFuncAttributeMaxDynamicSharedMemorySize, GEMM_SMEM);
    cudaFuncSetAttribute(attn_kernel,  cudaFuncAttributeMaxDynamicSharedMemorySize, attn_smem);

    cvt_kernel<<<4096, 256>>>(q, k, v, Wq, Wk, Wv, Wo);

    dim3 g1(MM / 128, EE / 128, 3);
    qkv_kernel<<<g1, 256, GEMM_SMEM>>>(bq, bk, bv);

    dim3 g2(SS / QT, HH, BB);
    attn_kernel<<<g2, 256, attn_smem>>>();

    dim3 g3(MM / 128, EE / 128, 1);
    oproj_kernel<<<g3, 256, GEMM_SMEM>>>(bo, (float*)d_out);
}

// round 10
// speedup vs baseline: 1.3605x; 1.0743x over previous
#include <cuda_runtime.h>
#include <cuda_fp16.h>
#include <cstdint>

// Problem constants
#define BB 4
#define SS 2048
#define EE 1024
#define HH 16
#define DD 64
#define MM (BB*SS)   // 8192 rows

// ---------------------------------------------------------------------------
// Scratch (device globals)
// ---------------------------------------------------------------------------
__device__ __half g_Q[MM * EE];
__device__ __half g_K[MM * EE];
__device__ __half g_V[MM * EE];
__device__ __half g_A[MM * EE];
__device__ __half g_X[3][MM * EE];   // fp16-converted inputs q,k,v
__device__ __half g_W[4][EE * EE];   // fp16-converted weights Wq,Wk,Wv,Wo

// ---------------------------------------------------------------------------
// PTX helpers (legacy mma.sync path — harness targets sm_100, no tcgen05)
// ---------------------------------------------------------------------------
__device__ __forceinline__ uint32_t smem_u32(const void* p) {
    return (uint32_t)__cvta_generic_to_shared(p);
}
__device__ __forceinline__ void ldmx4(uint32_t& r0, uint32_t& r1, uint32_t& r2,
                                      uint32_t& r3, uint32_t a) {
    asm volatile("ldmatrix.sync.aligned.m8n8.x4.shared.b16 {%0,%1,%2,%3}, [%4];\n"
                 : "=r"(r0), "=r"(r1), "=r"(r2), "=r"(r3) : "r"(a));
}
__device__ __forceinline__ void ldmx4t(uint32_t& r0, uint32_t& r1, uint32_t& r2,
                                       uint32_t& r3, uint32_t a) {
    asm volatile("ldmatrix.sync.aligned.m8n8.x4.trans.shared.b16 {%0,%1,%2,%3}, [%4];\n"
                 : "=r"(r0), "=r"(r1), "=r"(r2), "=r"(r3) : "r"(a));
}
__device__ __forceinline__ void mma16816(float* c, const uint32_t* a, const uint32_t* b) {
    asm volatile(
        "mma.sync.aligned.m16n8k16.row.col.f32.f16.f16.f32 "
        "{%0,%1,%2,%3}, {%4,%5,%6,%7}, {%8,%9}, {%0,%1,%2,%3};\n"
        : "+f"(c[0]), "+f"(c[1]), "+f"(c[2]), "+f"(c[3])
        : "r"(a[0]), "r"(a[1]), "r"(a[2]), "r"(a[3]), "r"(b[0]), "r"(b[1]));
}
__device__ __forceinline__ void cpa16(uint32_t dst, const void* src) {
    asm volatile("cp.async.cg.shared.global [%0], [%1], 16;\n" :: "r"(dst), "l"(src));
}

// ---- mbarrier pipeline primitives (Ampere-style full/empty rings) ----------
__device__ __forceinline__ void mbar_init(uint32_t mbar, uint32_t count) {
    asm volatile("mbarrier.init.shared.b64 [%0], %1;" :: "r"(mbar), "r"(count) : "memory");
}
__device__ __forceinline__ void mbar_arrive(uint32_t mbar) {
    asm volatile("mbarrier.arrive.shared.b64 _, [%0];" :: "r"(mbar) : "memory");
}
// Deferred arrive when this thread's prior cp.asyncs complete. .noinc is
// REQUIRED: the default form pre-increments the pending count (net zero vs the
// init count) and the barrier never flips -> deadlock (= round-8 timeout).
__device__ __forceinline__ void cp_mbar_arrive(uint32_t mbar) {
    asm volatile("cp.async.mbarrier.arrive.noinc.shared.b64 [%0];" :: "r"(mbar) : "memory");
}
__device__ __forceinline__ void mbar_wait(uint32_t mbar, uint32_t parity) {
    asm volatile(
        "{\n\t.reg .pred P;\n"
        "W%=:\n\tmbarrier.try_wait.parity.shared.b64 P, [%0], %1;\n"
        "\t@P bra D%=;\n\tbra W%=;\n"
        "D%=:\n\t}"
        :: "r"(mbar), "r"(parity) : "memory");
}

// ---------------------------------------------------------------------------
// fp32 -> fp16 conversion of all inputs/weights in one pass
// ---------------------------------------------------------------------------
__global__ void cvt_kernel(const float* q, const float* k, const float* v,
                           const float* Wq, const float* Wk, const float* Wv,
                           const float* Wo) {
    const long X4 = (long)MM * EE / 4;
    const long W4 = (long)EE * EE / 4;
    const long total = 3 * X4 + 4 * W4;
    for (long i = (long)blockIdx.x * blockDim.x + threadIdx.x; i < total;
         i += (long)gridDim.x * blockDim.x) {
        const float* src; __half* dst; long off;
        if (i < X4)          { src = q; dst = g_X[0]; off = i; }
        else if (i < 2 * X4) { src = k; dst = g_X[1]; off = i - X4; }
        else if (i < 3 * X4) { src = v; dst = g_X[2]; off = i - 2 * X4; }
        else {
            long j = i - 3 * X4;
            int w = (int)(j >> 18);
            off = j & (W4 - 1);
            src = (w == 0) ? Wq : (w == 1) ? Wk : (w == 2) ? Wv : Wo;
            dst = g_W[w];
        }
        const float4 f = *(const float4*)(src + off * 4);
        const __half2 h0 = __floats2half2_rn(f.x, f.y);
        const __half2 h1 = __floats2half2_rn(f.z, f.w);
        uint2 h;
        h.x = *(const uint32_t*)&h0;
        h.y = *(const uint32_t*)&h1;
        *(uint2*)(dst + off * 4) = h;
    }
}

// ---------------------------------------------------------------------------
// GEMM: C[M,N] = A[M,K]*W[N,K]^T + bias, fp16 in / fp32 accum
// Proven layout: BM=BN=128, BK=32, stride 40 halves (80B). 4-stage ring with
// mbarrier full/empty tracking — NO __syncthreads in the mainloop, so warps
// can skew and cover each other's latency gaps. 256 thr, 2 CTAs/SM.
// smem: [full[4] empty[4] pad to 128B][sA 4 stages][sB 4 stages]
// ---------------------------------------------------------------------------
#define BK 32
#define KST 40
#define STG 4
#define STAGE_H (128 * KST)                     // 5120 halves per operand/stage
#define GEMM_SMEM (128 + 2 * STG * STAGE_H * 2) // 82048 B

template <bool O16>
__device__ __forceinline__ void gemm_body(const __half* Ag, const __half* Wg,
                                          const float* biasg, void* Cg_) {
    extern __shared__ __align__(16) uint8_t smg[];
    const uint32_t base    = smem_u32(smg);
    const uint32_t mbFull  = base;        // 4 × 8B
    const uint32_t mbEmpty = base + 32;   // 4 × 8B
    __half* sA = (__half*)(smg + 128);
    __half* sB = sA + STG * STAGE_H;

    const int tid = threadIdx.x;
    const int bm = blockIdx.x, bn = blockIdx.y;
    const int warp = tid >> 5, lane = tid & 31;
    const int wm = warp & 3, wn = warp >> 2;

    if (tid == 0) {
#pragma unroll
        for (int i = 0; i < STG; i++) {
            mbar_init(mbFull + 8 * i, 256);
            mbar_init(mbEmpty + 8 * i, 256);
        }
    }
    __syncthreads();

    // cp.async mapping: row = tid/4 (0..63, +64), 16B chunk = tid&3
    const int lrow = tid >> 2;
    const int lch  = (tid & 3) * 8;          // halves
    const __half* gA = Ag + (long)(bm * 128) * EE;
    const __half* gB = Wg + (long)(bn * 128) * EE;
    const uint32_t sAb = smem_u32(sA);
    const uint32_t sBb = smem_u32(sB);

    const int NK = EE / BK;                  // 32

    auto produce = [&](int s) {
        const int buf = s & (STG - 1);
        mbar_wait(mbEmpty + 8 * buf, (uint32_t)(((s >> 2) & 1) ^ 1));
        const int kb = s * BK + lch;
        const uint32_t dA = sAb + (buf * STAGE_H + lrow * KST + lch) * 2;
        const uint32_t dB = sBb + (buf * STAGE_H + lrow * KST + lch) * 2;
        cpa16(dA,                gA + (long)lrow * EE + kb);
        cpa16(dA + 64 * KST * 2, gA + (long)(lrow + 64) * EE + kb);
        cpa16(dB,                gB + (long)lrow * EE + kb);
        cpa16(dB + 64 * KST * 2, gB + (long)(lrow + 64) * EE + kb);
        cp_mbar_arrive(mbFull + 8 * buf);
    };

    produce(0); produce(1); produce(2);

    float acc[2][8][4];
#pragma unroll
    for (int j = 0; j < 2; j++)
#pragma unroll
        for (int n = 0; n < 8; n++)
#pragma unroll
            for (int v = 0; v < 4; v++) acc[j][n][v] = 0.f;

    for (int kt = 0; kt < NK; kt++) {
        if (kt + 3 < NK) produce(kt + 3);
        const int buf = kt & (STG - 1);
        mbar_wait(mbFull + 8 * buf, (uint32_t)((kt >> 2) & 1));

        const __half* cA = sA + buf * STAGE_H;
        const __half* cB = sB + buf * STAGE_H;
#pragma unroll
        for (int ks = 0; ks < 2; ks++) {
            const int kb = ks * 16;
            uint32_t af[2][4];
#pragma unroll
            for (int j = 0; j < 2; j++) {
                const uint32_t ad = smem_u32(
                    cA + (wm * 32 + j * 16 + (lane & 15)) * KST + kb + (lane >> 4) * 8);
                ldmx4(af[j][0], af[j][1], af[j][2], af[j][3], ad);
            }
            uint32_t bf[8][2];
#pragma unroll
            for (int q = 0; q < 4; q++) {
                const int nrow = wn * 64 + q * 16 + (lane & 7) + ((lane >> 4) << 3);
                const int koff = ((lane >> 3) & 1) * 8;
                const uint32_t ad = smem_u32(cB + nrow * KST + kb + koff);
                ldmx4(bf[2 * q][0], bf[2 * q][1], bf[2 * q + 1][0], bf[2 * q + 1][1], ad);
            }
#pragma unroll
            for (int j = 0; j < 2; j++)
#pragma unroll
                for (int n = 0; n < 8; n++) mma16816(acc[j][n], af[j], bf[n]);
        }
        mbar_arrive(mbEmpty + 8 * buf);
    }

    // Epilogue: + bias, store
#pragma unroll
    for (int j = 0; j < 2; j++) {
#pragma unroll
        for (int n = 0; n < 8; n++) {
            const int row = bm * 128 + wm * 32 + j * 16 + (lane >> 2);
            const int col = bn * 128 + wn * 64 + n * 8 + (lane & 3) * 2;
            const float b0 = biasg[col], b1 = biasg[col + 1];
            const float c0 = acc[j][n][0] + b0, c1 = acc[j][n][1] + b1;
            const float c2 = acc[j][n][2] + b0, c3 = acc[j][n][3] + b1;
            if (O16) {
                __half* C = (__half*)Cg_;
                *(__half2*)(C + (long)row * EE + col)       = __floats2half2_rn(c0, c1);
                *(__half2*)(C + (long)(row + 8) * EE + col) = __floats2half2_rn(c2, c3);
            } else {
                float* C = (float*)Cg_;
                *(float2*)(C + (long)row * EE + col)       = make_float2(c0, c1);
                *(float2*)(C + (long)(row + 8) * EE + col) = make_float2(c2, c3);
            }
        }
    }
}

__global__ __launch_bounds__(256, 2) void qkv_kernel(const float* bq, const float* bk,
                                                     const float* bv) {
    const int z = blockIdx.z;
    const float* bias = (z == 0) ? bq : (z == 1) ? bk : bv;
    __half* O = (z == 0) ? g_Q : (z == 1) ? g_K : g_V;
    gemm_body<true>(g_X[z], g_W[z], bias, O);
}

__global__ __launch_bounds__(256, 2) void oproj_kernel(const float* bo, float* out) {
    gemm_body<false>(g_A, g_W[3], bo, out);
}

// ---------------------------------------------------------------------------
// Flash attention: CTA = (b, h, 128 queries), 8 warps x 16 q-rows, 2 CTAs/SM.
// 3-stage KV ring with mbarrier full/empty tracking — no __syncthreads in
// the mainloop, so warps skew and softmax gaps overlap other warps' MMAs.
// Q pre-scaled by scale*log2(e); exp via ex2.approx.f16x2.
// smem: [full[3] empty[3] pad 128B][sQ][sK 3 stages][sV 3 stages]
// ---------------------------------------------------------------------------
#define QT 128
#define KT 64
#define AST 72
#define KVSTG_H (KT * AST)
#define ATTN_SMEM (128 + (QT * AST + 6 * KVSTG_H) * 2)   // 73856 B

__global__ __launch_bounds__(256, 2) void attn_kernel() {
    extern __shared__ __align__(16) uint8_t sma[];
    const uint32_t base    = smem_u32(sma);
    const uint32_t mbFull  = base;        // 3 × 8B
    const uint32_t mbEmpty = base + 24;   // 3 × 8B
    __half* sQ = (__half*)(sma + 128);
    __half* sK = sQ + QT * AST;
    __half* sV = sK + 3 * KVSTG_H;

    const int tid  = threadIdx.x;
    const int warp = tid >> 5, lane = tid & 31;
    const int qbase = blockIdx.x * QT;
    const int h     = blockIdx.y;
    const int b     = blockIdx.z;
    const long rowbase = (long)b * SS;
    const int colbase  = h * DD;

    if (tid == 0) {
#pragma unroll
        for (int i = 0; i < 3; i++) {
            mbar_init(mbFull + 8 * i, 256);
            mbar_init(mbEmpty + 8 * i, 256);
        }
    }
    __syncthreads();

    const uint32_t sKb = smem_u32(sK);
    const uint32_t sVb = smem_u32(sV);

    const int krow = tid >> 3;
    const int kch  = (tid & 7) * 8;
    const int NT = SS / KT;               // 32

    auto produce = [&](int t) {
        const int buf = t % 3;
        mbar_wait(mbEmpty + 8 * buf, (uint32_t)(((t / 3) & 1) ^ 1));
        const long gb = (rowbase + t * KT) * EE + colbase + kch;
        const uint32_t dK = sKb + buf * KVSTG_H * 2 + (krow * AST + kch) * 2;
        const uint32_t dV = sVb + buf * KVSTG_H * 2 + (krow * AST + kch) * 2;
        cpa16(dK,                g_K + gb + (long)krow * EE);
        cpa16(dK + 32 * AST * 2, g_K + gb + (long)(krow + 32) * EE);
        cpa16(dV,                g_V + gb + (long)krow * EE);
        cpa16(dV + 32 * AST * 2, g_V + gb + (long)(krow + 32) * EE);
        cp_mbar_arrive(mbFull + 8 * buf);
    };

    produce(0); produce(1);

    // Stage Q tile [128 x 64]
    {
        const int lr = tid >> 3;
        const int lc = (tid & 7) * 8;
#pragma unroll
        for (int i = 0; i < 4; i++) {
            const int row = lr + i * 32;
            const uint4 v = *(const uint4*)(g_Q + (rowbase + qbase + row) * EE + colbase + lc);
            *(uint4*)(sQ + row * AST + lc) = v;
        }
    }
    __syncthreads();

    // Persistent Q fragments, pre-scaled by scale*log2(e)
    const float SC = 0.125f * 1.4426950408889634f;
    uint32_t qa[4][4];
    {
        const int wq = warp * 16;
        const __half2 sc2 = __floats2half2_rn(SC, SC);
#pragma unroll
        for (int kk = 0; kk < 4; kk++) {
            const uint32_t ad =
                smem_u32(sQ + (wq + (lane & 15)) * AST + kk * 16 + (lane >> 4) * 8);
            ldmx4(qa[kk][0], qa[kk][1], qa[kk][2], qa[kk][3], ad);
#pragma unroll
            for (int r = 0; r < 4; r++) {
                __half2 q2 = *(const __half2*)&qa[kk][r];
                q2 = __hmul2(q2, sc2);
                qa[kk][r] = *(const uint32_t*)&q2;
            }
        }
    }

    float oacc[8][4];
#pragma unroll
    for (int n = 0; n < 8; n++)
#pragma unroll
        for (int v = 0; v < 4; v++) oacc[n][v] = 0.f;
    float m0 = -1e30f, m1 = -1e30f, l0 = 0.f, l1 = 0.f;

    for (int t = 0; t < NT; t++) {
        if (t + 2 < NT) produce(t + 2);
        const int buf = t % 3;
        mbar_wait(mbFull + 8 * buf, (uint32_t)((t / 3) & 1));

        const __half* cK = sK + buf * KVSTG_H;
        const __half* cV = sV + buf * KVSTG_H;

        // S = Q K^T (log2 units: Q pre-scaled)
        float sacc[8][4];
#pragma unroll
        for (int n = 0; n < 8; n++)
#pragma unroll
            for (int v = 0; v < 4; v++) sacc[n][v] = 0.f;
#pragma unroll
        for (int kk = 0; kk < 4; kk++) {
            uint32_t kb[8][2];
#pragma unroll
            for (int q = 0; q < 4; q++) {
                const int nrow = q * 16 + (lane & 7) + ((lane >> 4) << 3);
                const int koff = ((lane >> 3) & 1) * 8;
                const uint32_t ad = smem_u32(cK + nrow * AST + kk * 16 + koff);
                ldmx4(kb[2 * q][0], kb[2 * q][1], kb[2 * q + 1][0], kb[2 * q + 1][1], ad);
            }
#pragma unroll
            for (int n = 0; n < 8; n++) mma16816(sacc[n], qa[kk], kb[n]);
        }

        // Online softmax in base-2 units
        float mx0 = -1e30f, mx1 = -1e30f;
#pragma unroll
        for (int n = 0; n < 8; n++) {
            mx0 = fmaxf(mx0, fmaxf(sacc[n][0], sacc[n][1]));
            mx1 = fmaxf(mx1, fmaxf(sacc[n][2], sacc[n][3]));
        }
        mx0 = fmaxf(mx0, __shfl_xor_sync(0xffffffffu, mx0, 1));
        mx0 = fmaxf(mx0, __shfl_xor_sync(0xffffffffu, mx0, 2));
        mx1 = fmaxf(mx1, __shfl_xor_sync(0xffffffffu, mx1, 1));
        mx1 = fmaxf(mx1, __shfl_xor_sync(0xffffffffu, mx1, 2));
        const float nm0 = fmaxf(m0, mx0);
        const float nm1 = fmaxf(m1, mx1);
        const float cr0 = exp2f(m0 - nm0);
        const float cr1 = exp2f(m1 - nm1);
        m0 = nm0; m1 = nm1;
        l0 *= cr0; l1 *= cr1;
#pragma unroll
        for (int n = 0; n < 8; n++) {
            oacc[n][0] *= cr0; oacc[n][1] *= cr0;
            oacc[n][2] *= cr1; oacc[n][3] *= cr1;
        }
        float rs0 = 0.f, rs1 = 0.f;
        uint32_t pa[8], pb[8];
#pragma unroll
        for (int n = 0; n < 8; n++) {
            const __half2 e01 =
                h2exp2(__floats2half2_rn(sacc[n][0] - m0, sacc[n][1] - m0));
            const __half2 e23 =
                h2exp2(__floats2half2_rn(sacc[n][2] - m1, sacc[n][3] - m1));
            pa[n] = *(const uint32_t*)&e01;
            pb[n] = *(const uint32_t*)&e23;
            const float2 f01 = __half22float2(e01);
            const float2 f23 = __half22float2(e23);
            rs0 += f01.x + f01.y;
            rs1 += f23.x + f23.y;
        }
        rs0 += __shfl_xor_sync(0xffffffffu, rs0, 1);
        rs0 += __shfl_xor_sync(0xffffffffu, rs0, 2);
        rs1 += __shfl_xor_sync(0xffffffffu, rs1, 1);
        rs1 += __shfl_xor_sync(0xffffffffu, rs1, 2);
        l0 += rs0; l1 += rs1;

        // O += P V (P already in A-fragment layout)
#pragma unroll
        for (int kk = 0; kk < 4; kk++) {
            const uint32_t af[4] = {pa[2 * kk], pb[2 * kk], pa[2 * kk + 1], pb[2 * kk + 1]};
            uint32_t vb[8][2];
#pragma unroll
            for (int pr = 0; pr < 4; pr++) {
                const int kvrow = kk * 16 + (((lane >> 3) & 1) << 3) + (lane & 7);
                const int dcol  = pr * 16 + ((lane >> 4) << 3);
                const uint32_t ad = smem_u32(cV + kvrow * AST + dcol);
                ldmx4t(vb[2 * pr][0], vb[2 * pr][1], vb[2 * pr + 1][0], vb[2 * pr + 1][1], ad);
            }
#pragma unroll
            for (int n = 0; n < 8; n++) mma16816(oacc[n], af, vb[n]);
        }
        mbar_arrive(mbEmpty + 8 * buf);
    }

    // Epilogue
    const float il0 = 1.f / l0, il1 = 1.f / l1;
    const int row = qbase + warp * 16 + (lane >> 2);
#pragma unroll
    for (int n = 0; n < 8; n++) {
        const int col = colbase + n * 8 + (lane & 3) * 2;
        *(__half2*)(g_A + (rowbase + row) * EE + col) =
            __floats2half2_rn(oacc[n][0] * il0, oacc[n][1] * il0);
        *(__half2*)(g_A + (rowbase + row + 8) * EE + col) =
            __floats2half2_rn(oacc[n][2] * il1, oacc[n][3] * il1);
    }
}

// ---------------------------------------------------------------------------
// Launch
// ---------------------------------------------------------------------------
extern "C" void kernel_launch(void* const* d_in, const int* in_sizes, int n_in,
                              void* d_out, int out_size) {
    (void)in_sizes; (void)n_in; (void)out_size;
    const float* q  = (const float*)d_in[0];
    const float* k  = (const float*)d_in[1];
    const float* v  = (const float*)d_in[2];
    const float* Wq = (const float*)d_in[3];
    const float* bq = (const float*)d_in[4];
    const float* Wk = (const float*)d_in[5];
    const float* bk = (const float*)d_in[6];
    const float* Wv = (const float*)d_in[7];
    const float* bv = (const float*)d_in[8];
    const float* Wo = (const float*)d_in[9];
    const float* bo = (const float*)d_in[10];

    cudaFuncSetAttribute(qkv_kernel,   cudaFuncAttributeMaxDynamicSharedMemorySize, GEMM_SMEM);
    cudaFuncSetAttribute(oproj_kernel, cudaFuncAttributeMaxDynamicSharedMemorySize, GEMM_SMEM);
    cudaFuncSetAttribute(attn_kernel,  cudaFuncAttributeMaxDynamicSharedMemorySize, ATTN_SMEM);

    cvt_kernel<<<4096, 256>>>(q, k, v, Wq, Wk, Wv, Wo);

    dim3 g1(MM / 128, EE / 128, 3);
    qkv_kernel<<<g1, 256, GEMM_SMEM>>>(bq, bk, bv);

    dim3 g2(SS / QT, HH, BB);
    attn_kernel<<<g2, 256, ATTN_SMEM>>>();

    dim3 g3(MM / 128, EE / 128, 1);
    oproj_kernel<<<g3, 256, GEMM_SMEM>>>(bo, (float*)d_out);
}